// round 4
// baseline (speedup 1.0000x reference)
#include <cuda_runtime.h>
#include <cuda_bf16.h>
#include <math.h>
#include <stdint.h>

// Problem constants
#define NTOK   4096
#define DMODEL 1024
#define DICT   16384
#define TOPK   8
#define TOPC   16      // candidates kept before fp32 rescore

// ---------------------------------------------------------------------------
// Scratch (__device__ globals; no allocation allowed)
// ---------------------------------------------------------------------------
__device__ int8_t g_xq[(size_t)NTOK * DMODEL];            // 4 MB
__device__ int8_t g_wq[(size_t)DICT * DMODEL];            // 16 MB
__device__ float  g_sx[NTOK];
__device__ float  g_sw[DICT];
__device__ __nv_bfloat16 g_cb[(size_t)NTOK * DICT];       // 128 MB (bf16 coeffs)
__device__ int   g_cand[NTOK * TOPC];
__device__ float g_vals[NTOK * TOPK];
__device__ int   g_idx[NTOK * TOPK];
__device__ float g_tokloss[NTOK];

// ---------------------------------------------------------------------------
// PTX helpers (sm_80-level only; legal at virtual arch compute_103)
// ---------------------------------------------------------------------------
__device__ __forceinline__ uint32_t smem_to_u32(const void* p) {
    uint32_t a;
    asm("{ .reg .u64 t; cvta.to.shared.u64 t, %1; cvt.u32.u64 %0, t; }"
        : "=r"(a) : "l"(p));
    return a;
}
__device__ __forceinline__ void cp_async16(uint32_t dst, const void* src) {
    asm volatile("cp.async.cg.shared.global [%0], [%1], 16;" :: "r"(dst), "l"(src));
}
#define CP_COMMIT() asm volatile("cp.async.commit_group;" ::: "memory")
#define CP_WAIT(n)  asm volatile("cp.async.wait_group %0;" :: "n"(n) : "memory")

__device__ __forceinline__ void ldsm_x4(uint32_t* r, uint32_t addr) {
    asm volatile("ldmatrix.sync.aligned.m8n8.x4.shared.b16 {%0,%1,%2,%3}, [%4];"
        : "=r"(r[0]), "=r"(r[1]), "=r"(r[2]), "=r"(r[3]) : "r"(addr));
}
// int8 IMMA: m16n8k32, s8 x s8 -> s32
__device__ __forceinline__ void mma_s8(int* d, const uint32_t* a,
                                       uint32_t b0, uint32_t b1, const int* c) {
    asm volatile("mma.sync.aligned.m16n8k32.row.col.s32.s8.s8.s32 "
        "{%0,%1,%2,%3}, {%4,%5,%6,%7}, {%8,%9}, {%10,%11,%12,%13};"
        : "=r"(d[0]), "=r"(d[1]), "=r"(d[2]), "=r"(d[3])
        : "r"(a[0]), "r"(a[1]), "r"(a[2]), "r"(a[3]),
          "r"(b0), "r"(b1),
          "r"(c[0]), "r"(c[1]), "r"(c[2]), "r"(c[3]));
}

// ---------------------------------------------------------------------------
// Kernel 0: per-row symmetric int8 quantization (1 block = 1 row of 1024)
// ---------------------------------------------------------------------------
__global__ __launch_bounds__(256)
void quant_kernel(const float* __restrict__ in, int8_t* __restrict__ q,
                  float* __restrict__ scales) {
    const int row = blockIdx.x;
    const int tid = threadIdx.x;
    const float4 v = reinterpret_cast<const float4*>(in + (size_t)row * DMODEL)[tid];
    float m = fmaxf(fmaxf(fabsf(v.x), fabsf(v.y)), fmaxf(fabsf(v.z), fabsf(v.w)));
    #pragma unroll
    for (int off = 16; off > 0; off >>= 1)
        m = fmaxf(m, __shfl_xor_sync(0xffffffffu, m, off));
    __shared__ float wmax[8];
    __shared__ float s_inv;
    if ((tid & 31) == 0) wmax[tid >> 5] = m;
    __syncthreads();
    if (tid == 0) {
        float mm = wmax[0];
        #pragma unroll
        for (int w = 1; w < 8; w++) mm = fmaxf(mm, wmax[w]);
        scales[row] = mm / 127.f;
        s_inv = (mm > 0.f) ? 127.f / mm : 0.f;
    }
    __syncthreads();
    const float inv = s_inv;
    char4 o;
    o.x = (char)max(-127, min(127, __float2int_rn(v.x * inv)));
    o.y = (char)max(-127, min(127, __float2int_rn(v.y * inv)));
    o.z = (char)max(-127, min(127, __float2int_rn(v.z * inv)));
    o.w = (char)max(-127, min(127, __float2int_rn(v.w * inv)));
    reinterpret_cast<char4*>(q + (size_t)row * DMODEL)[tid] = o;
}

// ---------------------------------------------------------------------------
// Kernel 1: int8 IMMA GEMM  C_bf16[m,n] = sx[m]*sw[n] * sum_d xq[m,d]*wq[n,d]
// CTA 128x128, K-chunk 64 (int8), 3-stage cp.async, 8 warps (2x4),
// warp tile 64x32, one __syncthreads per iteration
// ---------------------------------------------------------------------------
#define KC    64
#define NIT   (DMODEL / KC)        // 16
#define ROWB  80                   // smem row stride (64 data + 16 pad)
#define TILEB (128 * ROWB)         // 10240 B per operand tile
#define STAGEB (2 * TILEB)         // 20480 B per stage
#define GSMEM (3 * STAGEB)         // 61440 B dynamic

__global__ __launch_bounds__(256, 2)
void gemm_kernel(const int8_t* __restrict__ A, const int8_t* __restrict__ B,
                 const float* __restrict__ SX, const float* __restrict__ SW,
                 __nv_bfloat16* __restrict__ C) {
    extern __shared__ __align__(128) char sm[];
    __shared__ float ssx[128];
    __shared__ float ssw[128];
    const uint32_t smb = smem_to_u32(sm);
    const int tid  = threadIdx.x;
    const int wid  = tid >> 5;
    const int lane = tid & 31;
    const int wm   = wid >> 2;          // 0..1  -> 64 rows of m
    const int wn   = wid & 3;           // 0..3  -> 32 cols of n
    const int m0   = blockIdx.y * 128;
    const int n0   = blockIdx.x * 128;

    if (tid < 128) ssx[tid] = SX[m0 + tid];
    else           ssw[tid - 128] = SW[n0 + tid - 128];

    int acc[4][4][4];
    #pragma unroll
    for (int i = 0; i < 4; i++)
        #pragma unroll
        for (int j = 0; j < 4; j++)
            #pragma unroll
            for (int q = 0; q < 4; q++) acc[i][j][q] = 0;

    // stage loader: 4 x cp.async(16B) per thread (2 A + 2 B)
    auto load_stage = [&](int it) {
        const uint32_t aOff = smb + (it % 3) * STAGEB;
        const uint32_t bOff = aOff + TILEB;
        const int k0 = it * KC;
        #pragma unroll
        for (int i = 0; i < 2; i++) {
            int c = tid + i * 256;          // 0..511
            int row = c >> 2;               // 0..127
            int q = c & 3;                  // 16B chunk within 64B row
            cp_async16(aOff + row * ROWB + q * 16,
                       A + (size_t)(m0 + row) * DMODEL + k0 + q * 16);
            cp_async16(bOff + row * ROWB + q * 16,
                       B + (size_t)(n0 + row) * DMODEL + k0 + q * 16);
        }
        CP_COMMIT();
    };

    load_stage(0);
    load_stage(1);

    for (int s = 0; s < NIT; s++) {
        if (s + 2 < NIT) { CP_WAIT(1); } else { CP_WAIT(0); }
        __syncthreads();
        if (s + 2 < NIT) load_stage(s + 2);

        const uint32_t aOff = smb + (s % 3) * STAGEB;
        const uint32_t bOff = aOff + TILEB;

        #pragma unroll
        for (int kk = 0; kk < KC; kk += 32) {
            uint32_t af[4][4], bfr[2][4];
            #pragma unroll
            for (int mi = 0; mi < 4; mi++) {
                int row = wm * 64 + mi * 16 + (lane & 15);
                ldsm_x4(af[mi], aOff + row * ROWB + kk + (lane >> 4) * 16);
            }
            #pragma unroll
            for (int bp = 0; bp < 2; bp++) {
                int row = wn * 32 + bp * 16 + (lane & 15);
                ldsm_x4(bfr[bp], bOff + row * ROWB + kk + (lane >> 4) * 16);
            }
            #pragma unroll
            for (int mi = 0; mi < 4; mi++)
                #pragma unroll
                for (int ni = 0; ni < 4; ni++) {
                    int bp = ni >> 1, od = ni & 1;
                    mma_s8(acc[mi][ni], af[mi], bfr[bp][od], bfr[bp][od + 2],
                           acc[mi][ni]);
                }
        }
    }

    // epilogue: int32 -> float via per-row scales -> bf16x2 stores
    #pragma unroll
    for (int mi = 0; mi < 4; mi++) {
        #pragma unroll
        for (int ni = 0; ni < 4; ni++) {
            int mt = wm * 64 + mi * 16 + (lane >> 2);
            int nt = wn * 32 + ni * 8 + (lane & 3) * 2;
            float sa0 = ssx[mt], sa1 = ssx[mt + 8];
            float sb0 = ssw[nt], sb1 = ssw[nt + 1];
            __nv_bfloat162 h0 = __floats2bfloat162_rn(
                (float)acc[mi][ni][0] * sa0 * sb0,
                (float)acc[mi][ni][1] * sa0 * sb1);
            __nv_bfloat162 h1 = __floats2bfloat162_rn(
                (float)acc[mi][ni][2] * sa1 * sb0,
                (float)acc[mi][ni][3] * sa1 * sb1);
            *reinterpret_cast<__nv_bfloat162*>(C + (size_t)(m0 + mt) * DICT + n0 + nt) = h0;
            *reinterpret_cast<__nv_bfloat162*>(C + (size_t)(m0 + mt + 8) * DICT + n0 + nt) = h1;
        }
    }
}

// ---------------------------------------------------------------------------
// Kernel 2: per-token top-16 candidates from bf16 coeffs (block = 1 token)
// ---------------------------------------------------------------------------
__global__ __launch_bounds__(256)
void topc_kernel() {
    const int token = blockIdx.x;
    const __nv_bfloat16* __restrict__ row = g_cb + (size_t)token * DICT;
    const int tid = threadIdx.x;
    const int lane = tid & 31;
    const int wid = tid >> 5;

    float lv[TOPC];
    int   li[TOPC];
    #pragma unroll
    for (int i = 0; i < TOPC; i++) { lv[i] = -3.4e38f; li[i] = 0x7fffffff; }

    for (int itr = 0; itr < 8; itr++) {
        int j0 = (itr * 256 + tid) * 8;
        float4 raw = *reinterpret_cast<const float4*>(row + j0);
        const __nv_bfloat162* h = reinterpret_cast<const __nv_bfloat162*>(&raw);
        #pragma unroll
        for (int e = 0; e < 4; e++) {
            float v0 = __bfloat162float(h[e].x);
            float v1 = __bfloat162float(h[e].y);
            #pragma unroll
            for (int t = 0; t < 2; t++) {
                float v = t ? v1 : v0;
                int j = j0 + e * 2 + t;
                if (v > lv[TOPC - 1]) {
                    int pos = TOPC - 1;
                    #pragma unroll
                    for (int s = TOPC - 1; s > 0; s--) {
                        if (lv[s - 1] < v) { lv[s] = lv[s - 1]; li[s] = li[s - 1]; pos = s - 1; }
                    }
                    lv[pos] = v; li[pos] = j;
                }
            }
        }
    }

    __shared__ float wv[8];
    __shared__ int   wi[8];
    __shared__ int   sbi;

    int p = 0;
    for (int r = 0; r < TOPC; r++) {
        float v = (p < TOPC) ? lv[p] : -3.4e38f;
        int   i = (p < TOPC) ? li[p] : 0x7fffffff;
        #pragma unroll
        for (int off = 16; off > 0; off >>= 1) {
            float ov = __shfl_down_sync(0xffffffffu, v, off);
            int   oi = __shfl_down_sync(0xffffffffu, i, off);
            if (ov > v || (ov == v && oi < i)) { v = ov; i = oi; }
        }
        if (lane == 0) { wv[wid] = v; wi[wid] = i; }
        __syncthreads();
        if (tid == 0) {
            float bv = wv[0]; int bi = wi[0];
            #pragma unroll
            for (int w = 1; w < 8; w++)
                if (wv[w] > bv || (wv[w] == bv && wi[w] < bi)) { bv = wv[w]; bi = wi[w]; }
            sbi = bi;
            g_cand[token * TOPC + r] = bi;
        }
        __syncthreads();
        if (p < TOPC && li[p] == sbi) p++;
        __syncthreads();
    }
}

// ---------------------------------------------------------------------------
// Kernel 3: exact fp32 rescore of 16 candidates + top-8 select (block = token)
// ---------------------------------------------------------------------------
__global__ __launch_bounds__(256)
void rescore_kernel(const float* __restrict__ x, const float* __restrict__ W) {
    const int token = blockIdx.x;
    const int tid = threadIdx.x;
    const int lane = tid & 31;
    const int wid = tid >> 5;
    __shared__ float sx[DMODEL];
    __shared__ float cv[TOPC];
    __shared__ int   ci[TOPC];

    reinterpret_cast<float4*>(sx)[tid] = reinterpret_cast<const float4*>(
        x + (size_t)token * DMODEL)[tid];
    if (tid < TOPC) ci[tid] = g_cand[token * TOPC + tid];
    __syncthreads();

    #pragma unroll
    for (int cc = 0; cc < 2; cc++) {
        int c = wid * 2 + cc;
        const float4* wr = reinterpret_cast<const float4*>(W + (size_t)ci[c] * DMODEL);
        const float4* sx4 = reinterpret_cast<const float4*>(sx);
        float acc = 0.f;
        #pragma unroll
        for (int i = 0; i < 8; i++) {
            float4 a = sx4[lane + i * 32];
            float4 b = wr[lane + i * 32];
            acc = fmaf(a.x, b.x, acc);
            acc = fmaf(a.y, b.y, acc);
            acc = fmaf(a.z, b.z, acc);
            acc = fmaf(a.w, b.w, acc);
        }
        #pragma unroll
        for (int off = 16; off > 0; off >>= 1)
            acc += __shfl_xor_sync(0xffffffffu, acc, off);
        if (lane == 0) cv[c] = acc;
    }
    __syncthreads();

    if (tid == 0) {
        float v[TOPC]; int ix[TOPC];
        #pragma unroll
        for (int i = 0; i < TOPC; i++) { v[i] = cv[i]; ix[i] = ci[i]; }
        float run = 0.f;
        #pragma unroll
        for (int r = 0; r < TOPK; r++) {
            int best = 0;
            #pragma unroll
            for (int i = 1; i < TOPC; i++)
                if (v[i] > v[best] || (v[i] == v[best] && ix[i] < ix[best])) best = i;
            g_vals[token * TOPK + r] = v[best];
            g_idx[token * TOPK + r]  = ix[best];
            run += fabsf(v[best]);
            v[best] = -3.4e38f;
        }
        g_tokloss[token] = run;
    }
}

// ---------------------------------------------------------------------------
// Kernel 4: offset[token][d] = sum_k v_k * W_dict[idx_k][d]
// ---------------------------------------------------------------------------
__global__ __launch_bounds__(256)
void gather_kernel(const float* __restrict__ Wd, float* __restrict__ out) {
    const int token = blockIdx.x;
    const int tid = threadIdx.x;
    __shared__ float sv[TOPK];
    __shared__ int   si[TOPK];
    if (tid < TOPK) { sv[tid] = g_vals[token * TOPK + tid]; si[tid] = g_idx[token * TOPK + tid]; }
    __syncthreads();

    int d = tid * 4;
    float4 acc = make_float4(0.f, 0.f, 0.f, 0.f);
    #pragma unroll
    for (int k = 0; k < TOPK; k++) {
        const float4 w = *reinterpret_cast<const float4*>(&Wd[(size_t)si[k] * DMODEL + d]);
        float v = sv[k];
        acc.x = fmaf(v, w.x, acc.x);
        acc.y = fmaf(v, w.y, acc.y);
        acc.z = fmaf(v, w.z, acc.z);
        acc.w = fmaf(v, w.w, acc.w);
    }
    *reinterpret_cast<float4*>(&out[(size_t)token * DMODEL + d]) = acc;
}

// ---------------------------------------------------------------------------
// Kernel 5: sparsity loss (fixed-order tree reduction)
// ---------------------------------------------------------------------------
__global__ __launch_bounds__(256)
void loss_kernel(float* __restrict__ out, int out_size) {
    __shared__ float s[256];
    float acc = 0.f;
    for (int i = threadIdx.x; i < NTOK; i += 256) acc += g_tokloss[i];
    s[threadIdx.x] = acc;
    __syncthreads();
    for (int st = 128; st > 0; st >>= 1) {
        if (threadIdx.x < st) s[threadIdx.x] += s[threadIdx.x + st];
        __syncthreads();
    }
    if (threadIdx.x == 0 && out_size > NTOK * DMODEL) {
        out[out_size - 1] = s[0] / ((float)NTOK * (float)DICT);
    }
}

// ---------------------------------------------------------------------------
extern "C" void kernel_launch(void* const* d_in, const int* in_sizes, int n_in,
                              void* d_out, int out_size) {
    const float* x      = (const float*)d_in[0];   // [4096, 1024]
    const float* W_enc  = (const float*)d_in[1];   // [16384, 1024]
    const float* W_dict = (const float*)d_in[2];   // [16384, 1024]
    float* out = (float*)d_out;

    int8_t *xq, *wq;
    float *sx, *sw;
    __nv_bfloat16* cb;
    cudaGetSymbolAddress((void**)&xq, g_xq);
    cudaGetSymbolAddress((void**)&wq, g_wq);
    cudaGetSymbolAddress((void**)&sx, g_sx);
    cudaGetSymbolAddress((void**)&sw, g_sw);
    cudaGetSymbolAddress((void**)&cb, g_cb);

    cudaFuncSetAttribute(gemm_kernel, cudaFuncAttributeMaxDynamicSharedMemorySize, GSMEM);

    quant_kernel<<<NTOK, 256>>>(x, xq, sx);
    quant_kernel<<<DICT, 256>>>(W_enc, wq, sw);

    dim3 ggrid(DICT / 128, NTOK / 128);            // (128, 32)
    gemm_kernel<<<ggrid, 256, GSMEM>>>(xq, wq, sx, sw, cb);

    topc_kernel<<<NTOK, 256>>>();
    rescore_kernel<<<NTOK, 256>>>(x, W_enc);
    gather_kernel<<<NTOK, 256>>>(W_dict, out);
    loss_kernel<<<1, 256>>>(out, out_size);
}

// round 5
// speedup vs baseline: 1.2293x; 1.2293x over previous
#include <cuda_runtime.h>
#include <cuda_bf16.h>
#include <math.h>
#include <stdint.h>

// Problem constants
#define NTOK   4096
#define DMODEL 1024
#define DICT   16384
#define TOPK   8
#define TOPC   16      // candidates kept before fp32 rescore

// ---------------------------------------------------------------------------
// Scratch (__device__ globals; no allocation allowed)
// ---------------------------------------------------------------------------
__device__ __nv_bfloat16 g_xb[(size_t)NTOK * DMODEL];     // 8 MB
__device__ __nv_bfloat16 g_wb[(size_t)DICT * DMODEL];     // 32 MB
__device__ __nv_bfloat16 g_cb[(size_t)NTOK * DICT];       // 128 MB (bf16 coeffs)
__device__ int   g_cand[NTOK * TOPC];
__device__ float g_vals[NTOK * TOPK];
__device__ int   g_idx[NTOK * TOPK];
__device__ float g_tokloss[NTOK];

// ---------------------------------------------------------------------------
// PTX helpers (sm_80-level; legal at virtual arch compute_103)
// ---------------------------------------------------------------------------
__device__ __forceinline__ uint32_t smem_to_u32(const void* p) {
    uint32_t a;
    asm("{ .reg .u64 t; cvta.to.shared.u64 t, %1; cvt.u32.u64 %0, t; }"
        : "=r"(a) : "l"(p));
    return a;
}
__device__ __forceinline__ void cp_async16(uint32_t dst, const void* src) {
    asm volatile("cp.async.cg.shared.global [%0], [%1], 16;" :: "r"(dst), "l"(src));
}
#define CP_COMMIT() asm volatile("cp.async.commit_group;" ::: "memory")
#define CP_WAIT(n)  asm volatile("cp.async.wait_group %0;" :: "n"(n) : "memory")

__device__ __forceinline__ void ldsm_x4(uint32_t* r, uint32_t addr) {
    asm volatile("ldmatrix.sync.aligned.m8n8.x4.shared.b16 {%0,%1,%2,%3}, [%4];"
        : "=r"(r[0]), "=r"(r[1]), "=r"(r[2]), "=r"(r[3]) : "r"(addr));
}
__device__ __forceinline__ void mma_bf16(float* d, const uint32_t* a,
                                         uint32_t b0, uint32_t b1, const float* c) {
    asm volatile("mma.sync.aligned.m16n8k16.row.col.f32.bf16.bf16.f32 "
        "{%0,%1,%2,%3}, {%4,%5,%6,%7}, {%8,%9}, {%10,%11,%12,%13};"
        : "=f"(d[0]), "=f"(d[1]), "=f"(d[2]), "=f"(d[3])
        : "r"(a[0]), "r"(a[1]), "r"(a[2]), "r"(a[3]),
          "r"(b0), "r"(b1),
          "f"(c[0]), "f"(c[1]), "f"(c[2]), "f"(c[3]));
}

// ---------------------------------------------------------------------------
// Kernel 0: fp32 -> bf16 conversion
// ---------------------------------------------------------------------------
__global__ __launch_bounds__(256)
void conv_kernel(const float* __restrict__ in, __nv_bfloat16* __restrict__ out, int n4) {
    int i = blockIdx.x * 256 + threadIdx.x;
    if (i >= n4) return;
    float4 v = reinterpret_cast<const float4*>(in)[i];
    __nv_bfloat162 a = __floats2bfloat162_rn(v.x, v.y);
    __nv_bfloat162 b = __floats2bfloat162_rn(v.z, v.w);
    uint2 o;
    o.x = *reinterpret_cast<uint32_t*>(&a);
    o.y = *reinterpret_cast<uint32_t*>(&b);
    reinterpret_cast<uint2*>(out)[i] = o;
}

// ---------------------------------------------------------------------------
// Kernel 1: HMMA bf16 GEMM  C_bf16[m,n] = sum_d xb[m,d] * wb[n,d]
// CTA 128x256, 8 warps (2x4), warp tile 64x64, KC=32, 3-stage cp.async,
// one __syncthreads per iteration.  Per k16 step: 8 ldsm_x4 -> 32 HMMA.
// ---------------------------------------------------------------------------
#define BM    128
#define BN    256
#define KC    32
#define NIT   (DMODEL / KC)        // 32
#define ROWB  80                   // 64 B data (32 bf16) + 16 B pad
#define ATILE (BM * ROWB)          // 10240
#define BTILE (BN * ROWB)          // 20480
#define STAGEB (ATILE + BTILE)     // 30720
#define GSMEM (3 * STAGEB)         // 92160

__global__ __launch_bounds__(256, 1)
void gemm_kernel(const __nv_bfloat16* __restrict__ A, const __nv_bfloat16* __restrict__ B,
                 __nv_bfloat16* __restrict__ C) {
    extern __shared__ __align__(128) char sm[];
    const uint32_t smb = smem_to_u32(sm);
    const int tid  = threadIdx.x;
    const int wid  = tid >> 5;
    const int lane = tid & 31;
    const int wm   = wid & 1;           // 0..1 -> 64 rows of m
    const int wn   = wid >> 1;          // 0..3 -> 64 cols of n
    const int m0   = blockIdx.y * BM;
    const int n0   = blockIdx.x * BN;

    float acc[4][8][4];
    #pragma unroll
    for (int i = 0; i < 4; i++)
        #pragma unroll
        for (int j = 0; j < 8; j++)
            #pragma unroll
            for (int q = 0; q < 4; q++) acc[i][j][q] = 0.f;

    // stage loader: A = 512 chunks (2/thread), B = 1024 chunks (4/thread)
    auto load_stage = [&](int it) {
        const uint32_t aOff = smb + (it % 3) * STAGEB;
        const uint32_t bOff = aOff + ATILE;
        const int k0 = it * KC;
        #pragma unroll
        for (int i = 0; i < 2; i++) {
            int c = tid + i * 256;          // 0..511
            int row = c >> 2;               // 0..127
            int q = c & 3;
            cp_async16(aOff + row * ROWB + q * 16,
                       A + (size_t)(m0 + row) * DMODEL + k0 + q * 8);
        }
        #pragma unroll
        for (int i = 0; i < 4; i++) {
            int c = tid + i * 256;          // 0..1023
            int row = c >> 2;               // 0..255
            int q = c & 3;
            cp_async16(bOff + row * ROWB + q * 16,
                       B + (size_t)(n0 + row) * DMODEL + k0 + q * 8);
        }
        CP_COMMIT();
    };

    load_stage(0);
    load_stage(1);

    for (int s = 0; s < NIT; s++) {
        if (s + 2 < NIT) { CP_WAIT(1); } else { CP_WAIT(0); }
        __syncthreads();
        if (s + 2 < NIT) load_stage(s + 2);

        const uint32_t aOff = smb + (s % 3) * STAGEB;
        const uint32_t bOff = aOff + ATILE;

        #pragma unroll
        for (int kk = 0; kk < KC; kk += 16) {
            uint32_t af[4][4], bfr[4][4];
            #pragma unroll
            for (int mi = 0; mi < 4; mi++) {
                int row = wm * 64 + mi * 16 + (lane & 15);
                ldsm_x4(af[mi], aOff + row * ROWB + kk * 2 + (lane >> 4) * 16);
            }
            #pragma unroll
            for (int bi = 0; bi < 4; bi++) {
                int row = wn * 64 + bi * 16 + (lane & 15);
                ldsm_x4(bfr[bi], bOff + row * ROWB + kk * 2 + (lane >> 4) * 16);
            }
            #pragma unroll
            for (int mi = 0; mi < 4; mi++)
                #pragma unroll
                for (int ni = 0; ni < 8; ni++) {
                    int bp = ni >> 1, od = ni & 1;
                    mma_bf16(acc[mi][ni], af[mi], bfr[bp][od], bfr[bp][od + 2],
                             acc[mi][ni]);
                }
        }
    }

    // epilogue: fp32 -> bf16, direct gmem stores (bf16x2 per store)
    #pragma unroll
    for (int mi = 0; mi < 4; mi++) {
        #pragma unroll
        for (int ni = 0; ni < 8; ni++) {
            int m = m0 + wm * 64 + mi * 16 + (lane >> 2);
            int n = n0 + wn * 64 + ni * 8 + (lane & 3) * 2;
            __nv_bfloat162 h0 = __floats2bfloat162_rn(acc[mi][ni][0], acc[mi][ni][1]);
            __nv_bfloat162 h1 = __floats2bfloat162_rn(acc[mi][ni][2], acc[mi][ni][3]);
            *reinterpret_cast<__nv_bfloat162*>(C + (size_t)m * DICT + n) = h0;
            *reinterpret_cast<__nv_bfloat162*>(C + (size_t)(m + 8) * DICT + n) = h1;
        }
    }
}

// ---------------------------------------------------------------------------
// Kernel 2: per-token top-16 candidates from bf16 coeffs (block = 1 token)
// ---------------------------------------------------------------------------
__global__ __launch_bounds__(256)
void topc_kernel() {
    const int token = blockIdx.x;
    const __nv_bfloat16* __restrict__ row = g_cb + (size_t)token * DICT;
    const int tid = threadIdx.x;
    const int lane = tid & 31;
    const int wid = tid >> 5;

    float lv[TOPC];
    int   li[TOPC];
    #pragma unroll
    for (int i = 0; i < TOPC; i++) { lv[i] = -3.4e38f; li[i] = 0x7fffffff; }

    for (int itr = 0; itr < 8; itr++) {
        int j0 = (itr * 256 + tid) * 8;
        float4 raw = *reinterpret_cast<const float4*>(row + j0);
        const __nv_bfloat162* h = reinterpret_cast<const __nv_bfloat162*>(&raw);
        #pragma unroll
        for (int e = 0; e < 4; e++) {
            float v0 = __bfloat162float(h[e].x);
            float v1 = __bfloat162float(h[e].y);
            #pragma unroll
            for (int t = 0; t < 2; t++) {
                float v = t ? v1 : v0;
                int j = j0 + e * 2 + t;
                if (v > lv[TOPC - 1]) {
                    int pos = TOPC - 1;
                    #pragma unroll
                    for (int s = TOPC - 1; s > 0; s--) {
                        if (lv[s - 1] < v) { lv[s] = lv[s - 1]; li[s] = li[s - 1]; pos = s - 1; }
                    }
                    lv[pos] = v; li[pos] = j;
                }
            }
        }
    }

    __shared__ float wv[8];
    __shared__ int   wi[8];
    __shared__ int   sbi;

    int p = 0;
    for (int r = 0; r < TOPC; r++) {
        float v = (p < TOPC) ? lv[p] : -3.4e38f;
        int   i = (p < TOPC) ? li[p] : 0x7fffffff;
        #pragma unroll
        for (int off = 16; off > 0; off >>= 1) {
            float ov = __shfl_down_sync(0xffffffffu, v, off);
            int   oi = __shfl_down_sync(0xffffffffu, i, off);
            if (ov > v || (ov == v && oi < i)) { v = ov; i = oi; }
        }
        if (lane == 0) { wv[wid] = v; wi[wid] = i; }
        __syncthreads();
        if (tid == 0) {
            float bv = wv[0]; int bi = wi[0];
            #pragma unroll
            for (int w = 1; w < 8; w++)
                if (wv[w] > bv || (wv[w] == bv && wi[w] < bi)) { bv = wv[w]; bi = wi[w]; }
            sbi = bi;
            g_cand[token * TOPC + r] = bi;
        }
        __syncthreads();
        if (p < TOPC && li[p] == sbi) p++;
        __syncthreads();
    }
}

// ---------------------------------------------------------------------------
// Kernel 3: exact fp32 rescore of 16 candidates + top-8 select (block = token)
// ---------------------------------------------------------------------------
__global__ __launch_bounds__(256)
void rescore_kernel(const float* __restrict__ x, const float* __restrict__ W) {
    const int token = blockIdx.x;
    const int tid = threadIdx.x;
    const int lane = tid & 31;
    const int wid = tid >> 5;
    __shared__ float sx[DMODEL];
    __shared__ float cv[TOPC];
    __shared__ int   ci[TOPC];

    reinterpret_cast<float4*>(sx)[tid] = reinterpret_cast<const float4*>(
        x + (size_t)token * DMODEL)[tid];
    if (tid < TOPC) ci[tid] = g_cand[token * TOPC + tid];
    __syncthreads();

    #pragma unroll
    for (int cc = 0; cc < 2; cc++) {
        int c = wid * 2 + cc;
        const float4* wr = reinterpret_cast<const float4*>(W + (size_t)ci[c] * DMODEL);
        const float4* sx4 = reinterpret_cast<const float4*>(sx);
        float acc = 0.f;
        #pragma unroll
        for (int i = 0; i < 8; i++) {
            float4 a = sx4[lane + i * 32];
            float4 b = wr[lane + i * 32];
            acc = fmaf(a.x, b.x, acc);
            acc = fmaf(a.y, b.y, acc);
            acc = fmaf(a.z, b.z, acc);
            acc = fmaf(a.w, b.w, acc);
        }
        #pragma unroll
        for (int off = 16; off > 0; off >>= 1)
            acc += __shfl_xor_sync(0xffffffffu, acc, off);
        if (lane == 0) cv[c] = acc;
    }
    __syncthreads();

    if (tid == 0) {
        float v[TOPC]; int ix[TOPC];
        #pragma unroll
        for (int i = 0; i < TOPC; i++) { v[i] = cv[i]; ix[i] = ci[i]; }
        float run = 0.f;
        #pragma unroll
        for (int r = 0; r < TOPK; r++) {
            int best = 0;
            #pragma unroll
            for (int i = 1; i < TOPC; i++)
                if (v[i] > v[best] || (v[i] == v[best] && ix[i] < ix[best])) best = i;
            g_vals[token * TOPK + r] = v[best];
            g_idx[token * TOPK + r]  = ix[best];
            run += fabsf(v[best]);
            v[best] = -3.4e38f;
        }
        g_tokloss[token] = run;
    }
}

// ---------------------------------------------------------------------------
// Kernel 4: offset[token][d] = sum_k v_k * W_dict[idx_k][d]
// ---------------------------------------------------------------------------
__global__ __launch_bounds__(256)
void gather_kernel(const float* __restrict__ Wd, float* __restrict__ out) {
    const int token = blockIdx.x;
    const int tid = threadIdx.x;
    __shared__ float sv[TOPK];
    __shared__ int   si[TOPK];
    if (tid < TOPK) { sv[tid] = g_vals[token * TOPK + tid]; si[tid] = g_idx[token * TOPK + tid]; }
    __syncthreads();

    int d = tid * 4;
    float4 acc = make_float4(0.f, 0.f, 0.f, 0.f);
    #pragma unroll
    for (int k = 0; k < TOPK; k++) {
        const float4 w = *reinterpret_cast<const float4*>(&Wd[(size_t)si[k] * DMODEL + d]);
        float v = sv[k];
        acc.x = fmaf(v, w.x, acc.x);
        acc.y = fmaf(v, w.y, acc.y);
        acc.z = fmaf(v, w.z, acc.z);
        acc.w = fmaf(v, w.w, acc.w);
    }
    *reinterpret_cast<float4*>(&out[(size_t)token * DMODEL + d]) = acc;
}

// ---------------------------------------------------------------------------
// Kernel 5: sparsity loss (fixed-order tree reduction)
// ---------------------------------------------------------------------------
__global__ __launch_bounds__(256)
void loss_kernel(float* __restrict__ out, int out_size) {
    __shared__ float s[256];
    float acc = 0.f;
    for (int i = threadIdx.x; i < NTOK; i += 256) acc += g_tokloss[i];
    s[threadIdx.x] = acc;
    __syncthreads();
    for (int st = 128; st > 0; st >>= 1) {
        if (threadIdx.x < st) s[threadIdx.x] += s[threadIdx.x + st];
        __syncthreads();
    }
    if (threadIdx.x == 0 && out_size > NTOK * DMODEL) {
        out[out_size - 1] = s[0] / ((float)NTOK * (float)DICT);
    }
}

// ---------------------------------------------------------------------------
extern "C" void kernel_launch(void* const* d_in, const int* in_sizes, int n_in,
                              void* d_out, int out_size) {
    const float* x      = (const float*)d_in[0];   // [4096, 1024]
    const float* W_enc  = (const float*)d_in[1];   // [16384, 1024]
    const float* W_dict = (const float*)d_in[2];   // [16384, 1024]
    float* out = (float*)d_out;

    __nv_bfloat16 *xb, *wb, *cb;
    cudaGetSymbolAddress((void**)&xb, g_xb);
    cudaGetSymbolAddress((void**)&wb, g_wb);
    cudaGetSymbolAddress((void**)&cb, g_cb);

    cudaFuncSetAttribute(gemm_kernel, cudaFuncAttributeMaxDynamicSharedMemorySize, GSMEM);

    conv_kernel<<<(NTOK * DMODEL / 4 + 255) / 256, 256>>>(x, xb, NTOK * DMODEL / 4);
    conv_kernel<<<(DICT * DMODEL / 4 + 255) / 256, 256>>>(W_enc, wb, DICT * DMODEL / 4);

    dim3 ggrid(DICT / BN, NTOK / BM);              // (64, 32)
    gemm_kernel<<<ggrid, 256, GSMEM>>>(xb, wb, cb);

    topc_kernel<<<NTOK, 256>>>();
    rescore_kernel<<<NTOK, 256>>>(x, W_enc);
    gather_kernel<<<NTOK, 256>>>(W_dict, out);
    loss_kernel<<<1, 256>>>(out, out_size);
}

// round 6
// speedup vs baseline: 1.2809x; 1.0419x over previous
#include <cuda_runtime.h>
#include <cuda_fp16.h>
#include <math.h>
#include <stdint.h>

// Problem constants
#define NTOK   4096
#define DMODEL 1024
#define DICT   16384
#define TOPK   8
#define TOPC   16      // candidates kept before fp32 rescore

// ---------------------------------------------------------------------------
// Scratch (__device__ globals; no allocation allowed)
// ---------------------------------------------------------------------------
__device__ __half g_xh[(size_t)NTOK * DMODEL];        // 8 MB
__device__ __half g_wh[(size_t)DICT * DMODEL];        // 32 MB
__device__ __half g_ch[(size_t)NTOK * DICT];          // 128 MB (f16 coeffs)
__device__ int   g_cand[NTOK * TOPC];
__device__ float g_vals[NTOK * TOPK];
__device__ int   g_idx[NTOK * TOPK];
__device__ float g_tokloss[NTOK];

// ---------------------------------------------------------------------------
// PTX helpers (sm_80-level; legal at virtual arch compute_103)
// ---------------------------------------------------------------------------
__device__ __forceinline__ uint32_t smem_to_u32(const void* p) {
    uint32_t a;
    asm("{ .reg .u64 t; cvta.to.shared.u64 t, %1; cvt.u32.u64 %0, t; }"
        : "=r"(a) : "l"(p));
    return a;
}
__device__ __forceinline__ void cp_async16(uint32_t dst, const void* src) {
    asm volatile("cp.async.cg.shared.global [%0], [%1], 16;" :: "r"(dst), "l"(src));
}
#define CP_COMMIT() asm volatile("cp.async.commit_group;" ::: "memory")
#define CP_WAIT(n)  asm volatile("cp.async.wait_group %0;" :: "n"(n) : "memory")

__device__ __forceinline__ void ldsm_x4(uint32_t* r, uint32_t addr) {
    asm volatile("ldmatrix.sync.aligned.m8n8.x4.shared.b16 {%0,%1,%2,%3}, [%4];"
        : "=r"(r[0]), "=r"(r[1]), "=r"(r[2]), "=r"(r[3]) : "r"(addr));
}
__device__ __forceinline__ void ldsm_x2(uint32_t* r, uint32_t addr) {
    asm volatile("ldmatrix.sync.aligned.m8n8.x2.shared.b16 {%0,%1}, [%2];"
        : "=r"(r[0]), "=r"(r[1]) : "r"(addr));
}
// f16 x f16 -> f16 accumulate (D,C are 2 regs of f16x2)
__device__ __forceinline__ void mma_f16acc(uint32_t* d, const uint32_t* a,
                                           uint32_t b0, uint32_t b1) {
    asm volatile("mma.sync.aligned.m16n8k16.row.col.f16.f16.f16.f16 "
        "{%0,%1}, {%2,%3,%4,%5}, {%6,%7}, {%0,%1};"
        : "+r"(d[0]), "+r"(d[1])
        : "r"(a[0]), "r"(a[1]), "r"(a[2]), "r"(a[3]),
          "r"(b0), "r"(b1));
}

// ---------------------------------------------------------------------------
// Kernel 0: fp32 -> f16 conversion
// ---------------------------------------------------------------------------
__global__ __launch_bounds__(256)
void conv_kernel(const float* __restrict__ in, __half* __restrict__ out, int n4) {
    int i = blockIdx.x * 256 + threadIdx.x;
    if (i >= n4) return;
    float4 v = reinterpret_cast<const float4*>(in)[i];
    __half2 a = __floats2half2_rn(v.x, v.y);
    __half2 b = __floats2half2_rn(v.z, v.w);
    uint2 o;
    o.x = *reinterpret_cast<uint32_t*>(&a);
    o.y = *reinterpret_cast<uint32_t*>(&b);
    reinterpret_cast<uint2*>(out)[i] = o;
}

// ---------------------------------------------------------------------------
// Kernel 1: HMMA f16 GEMM (f16 accumulate)  C_f16[m,n] = sum_d xh[m,d]*wh[n,d]
// CTA 128x128, KC=32, 3-stage cp.async, 8 warps (2x4), warp tile 64x32
// ---------------------------------------------------------------------------
#define KC    32
#define NIT   (DMODEL / KC)        // 32
#define ROWB  80                   // 64 B data (32 f16) + 16 B pad
#define TILEB (128 * ROWB)         // 10240
#define STAGEB (2 * TILEB)         // 20480
#define GSMEM (3 * STAGEB)         // 61440

__global__ __launch_bounds__(256, 2)
void gemm_kernel(const __half* __restrict__ A, const __half* __restrict__ B,
                 __half* __restrict__ C) {
    extern __shared__ __align__(128) char sm[];
    const uint32_t smb = smem_to_u32(sm);
    const int tid  = threadIdx.x;
    const int wid  = tid >> 5;
    const int lane = tid & 31;
    const int wm   = wid >> 2;          // 0..1 -> 64 rows of m
    const int wn   = wid & 3;           // 0..3 -> 32 cols of n
    const int m0   = blockIdx.y * 128;
    const int n0   = blockIdx.x * 128;

    uint32_t acc[4][4][2];              // f16x2 accumulators
    #pragma unroll
    for (int i = 0; i < 4; i++)
        #pragma unroll
        for (int j = 0; j < 4; j++) { acc[i][j][0] = 0u; acc[i][j][1] = 0u; }

    auto load_stage = [&](int it) {
        const uint32_t aOff = smb + (it % 3) * STAGEB;
        const uint32_t bOff = aOff + TILEB;
        const int k0 = it * KC;
        #pragma unroll
        for (int i = 0; i < 2; i++) {
            int c = tid + i * 256;          // 0..511
            int row = c >> 2;               // 0..127
            int q = c & 3;
            cp_async16(aOff + row * ROWB + q * 16,
                       A + (size_t)(m0 + row) * DMODEL + k0 + q * 8);
            cp_async16(bOff + row * ROWB + q * 16,
                       B + (size_t)(n0 + row) * DMODEL + k0 + q * 8);
        }
        CP_COMMIT();
    };

    load_stage(0);
    load_stage(1);

    for (int s = 0; s < NIT; s++) {
        if (s + 1 < NIT) { CP_WAIT(1); } else { CP_WAIT(0); }
        __syncthreads();
        if (s + 2 < NIT) load_stage(s + 2);

        const uint32_t aOff = smb + (s % 3) * STAGEB;
        const uint32_t bOff = aOff + TILEB;

        #pragma unroll
        for (int kk = 0; kk < KC; kk += 16) {
            uint32_t af[4][4], bfr[4][2];
            #pragma unroll
            for (int mi = 0; mi < 4; mi++) {
                int row = wm * 64 + mi * 16 + (lane & 15);
                ldsm_x4(af[mi], aOff + row * ROWB + kk * 2 + (lane >> 4) * 16);
            }
            #pragma unroll
            for (int ni = 0; ni < 4; ni++) {
                int row = wn * 32 + ni * 8 + (lane & 7);
                ldsm_x2(bfr[ni], bOff + row * ROWB + kk * 2 + ((lane >> 3) & 1) * 16);
            }
            #pragma unroll
            for (int mi = 0; mi < 4; mi++)
                #pragma unroll
                for (int ni = 0; ni < 4; ni++)
                    mma_f16acc(acc[mi][ni], af[mi], bfr[ni][0], bfr[ni][1]);
        }
    }

    // epilogue: accumulator registers ARE f16x2 pairs -> direct 4B stores
    #pragma unroll
    for (int mi = 0; mi < 4; mi++) {
        #pragma unroll
        for (int ni = 0; ni < 4; ni++) {
            int m = m0 + wm * 64 + mi * 16 + (lane >> 2);
            int n = n0 + wn * 32 + ni * 8 + (lane & 3) * 2;
            *reinterpret_cast<uint32_t*>(C + (size_t)m * DICT + n) = acc[mi][ni][0];
            *reinterpret_cast<uint32_t*>(C + (size_t)(m + 8) * DICT + n) = acc[mi][ni][1];
        }
    }
}

// ---------------------------------------------------------------------------
// Kernel 2: per-token top-16 candidates from f16 coeffs (block = 1 token)
// ---------------------------------------------------------------------------
__global__ __launch_bounds__(256)
void topc_kernel() {
    const int token = blockIdx.x;
    const __half* __restrict__ row = g_ch + (size_t)token * DICT;
    const int tid = threadIdx.x;
    const int lane = tid & 31;
    const int wid = tid >> 5;

    float lv[TOPC];
    int   li[TOPC];
    #pragma unroll
    for (int i = 0; i < TOPC; i++) { lv[i] = -3.4e38f; li[i] = 0x7fffffff; }

    for (int itr = 0; itr < 8; itr++) {
        int j0 = (itr * 256 + tid) * 8;
        float4 raw = *reinterpret_cast<const float4*>(row + j0);
        const __half2* h = reinterpret_cast<const __half2*>(&raw);
        #pragma unroll
        for (int e = 0; e < 4; e++) {
            float2 f = __half22float2(h[e]);
            #pragma unroll
            for (int t = 0; t < 2; t++) {
                float v = t ? f.y : f.x;
                int j = j0 + e * 2 + t;
                if (v > lv[TOPC - 1]) {
                    int pos = TOPC - 1;
                    #pragma unroll
                    for (int s = TOPC - 1; s > 0; s--) {
                        if (lv[s - 1] < v) { lv[s] = lv[s - 1]; li[s] = li[s - 1]; pos = s - 1; }
                    }
                    lv[pos] = v; li[pos] = j;
                }
            }
        }
    }

    __shared__ float wv[8];
    __shared__ int   wi[8];
    __shared__ int   sbi;

    int p = 0;
    for (int r = 0; r < TOPC; r++) {
        float v = (p < TOPC) ? lv[p] : -3.4e38f;
        int   i = (p < TOPC) ? li[p] : 0x7fffffff;
        #pragma unroll
        for (int off = 16; off > 0; off >>= 1) {
            float ov = __shfl_down_sync(0xffffffffu, v, off);
            int   oi = __shfl_down_sync(0xffffffffu, i, off);
            if (ov > v || (ov == v && oi < i)) { v = ov; i = oi; }
        }
        if (lane == 0) { wv[wid] = v; wi[wid] = i; }
        __syncthreads();
        if (tid == 0) {
            float bv = wv[0]; int bi = wi[0];
            #pragma unroll
            for (int w = 1; w < 8; w++)
                if (wv[w] > bv || (wv[w] == bv && wi[w] < bi)) { bv = wv[w]; bi = wi[w]; }
            sbi = bi;
            g_cand[token * TOPC + r] = bi;
        }
        __syncthreads();
        if (p < TOPC && li[p] == sbi) p++;
        __syncthreads();
    }
}

// ---------------------------------------------------------------------------
// Kernel 3: exact fp32 rescore of 16 candidates + top-8 select (block = token)
// ---------------------------------------------------------------------------
__global__ __launch_bounds__(256)
void rescore_kernel(const float* __restrict__ x, const float* __restrict__ W) {
    const int token = blockIdx.x;
    const int tid = threadIdx.x;
    const int lane = tid & 31;
    const int wid = tid >> 5;
    __shared__ float sx[DMODEL];
    __shared__ float cv[TOPC];
    __shared__ int   ci[TOPC];

    reinterpret_cast<float4*>(sx)[tid] = reinterpret_cast<const float4*>(
        x + (size_t)token * DMODEL)[tid];
    if (tid < TOPC) ci[tid] = g_cand[token * TOPC + tid];
    __syncthreads();

    #pragma unroll
    for (int cc = 0; cc < 2; cc++) {
        int c = wid * 2 + cc;
        const float4* wr = reinterpret_cast<const float4*>(W + (size_t)ci[c] * DMODEL);
        const float4* sx4 = reinterpret_cast<const float4*>(sx);
        float acc = 0.f;
        #pragma unroll
        for (int i = 0; i < 8; i++) {
            float4 a = sx4[lane + i * 32];
            float4 b = wr[lane + i * 32];
            acc = fmaf(a.x, b.x, acc);
            acc = fmaf(a.y, b.y, acc);
            acc = fmaf(a.z, b.z, acc);
            acc = fmaf(a.w, b.w, acc);
        }
        #pragma unroll
        for (int off = 16; off > 0; off >>= 1)
            acc += __shfl_xor_sync(0xffffffffu, acc, off);
        if (lane == 0) cv[c] = acc;
    }
    __syncthreads();

    if (tid == 0) {
        float v[TOPC]; int ix[TOPC];
        #pragma unroll
        for (int i = 0; i < TOPC; i++) { v[i] = cv[i]; ix[i] = ci[i]; }
        float run = 0.f;
        #pragma unroll
        for (int r = 0; r < TOPK; r++) {
            int best = 0;
            #pragma unroll
            for (int i = 1; i < TOPC; i++)
                if (v[i] > v[best] || (v[i] == v[best] && ix[i] < ix[best])) best = i;
            g_vals[token * TOPK + r] = v[best];
            g_idx[token * TOPK + r]  = ix[best];
            run += fabsf(v[best]);
            v[best] = -3.4e38f;
        }
        g_tokloss[token] = run;
    }
}

// ---------------------------------------------------------------------------
// Kernel 4: offset[token][d] = sum_k v_k * W_dict[idx_k][d]
// ---------------------------------------------------------------------------
__global__ __launch_bounds__(256)
void gather_kernel(const float* __restrict__ Wd, float* __restrict__ out) {
    const int token = blockIdx.x;
    const int tid = threadIdx.x;
    __shared__ float sv[TOPK];
    __shared__ int   si[TOPK];
    if (tid < TOPK) { sv[tid] = g_vals[token * TOPK + tid]; si[tid] = g_idx[token * TOPK + tid]; }
    __syncthreads();

    int d = tid * 4;
    float4 acc = make_float4(0.f, 0.f, 0.f, 0.f);
    #pragma unroll
    for (int k = 0; k < TOPK; k++) {
        const float4 w = *reinterpret_cast<const float4*>(&Wd[(size_t)si[k] * DMODEL + d]);
        float v = sv[k];
        acc.x = fmaf(v, w.x, acc.x);
        acc.y = fmaf(v, w.y, acc.y);
        acc.z = fmaf(v, w.z, acc.z);
        acc.w = fmaf(v, w.w, acc.w);
    }
    *reinterpret_cast<float4*>(&out[(size_t)token * DMODEL + d]) = acc;
}

// ---------------------------------------------------------------------------
// Kernel 5: sparsity loss (fixed-order tree reduction)
// ---------------------------------------------------------------------------
__global__ __launch_bounds__(256)
void loss_kernel(float* __restrict__ out, int out_size) {
    __shared__ float s[256];
    float acc = 0.f;
    for (int i = threadIdx.x; i < NTOK; i += 256) acc += g_tokloss[i];
    s[threadIdx.x] = acc;
    __syncthreads();
    for (int st = 128; st > 0; st >>= 1) {
        if (threadIdx.x < st) s[threadIdx.x] += s[threadIdx.x + st];
        __syncthreads();
    }
    if (threadIdx.x == 0 && out_size > NTOK * DMODEL) {
        out[out_size - 1] = s[0] / ((float)NTOK * (float)DICT);
    }
}

// ---------------------------------------------------------------------------
extern "C" void kernel_launch(void* const* d_in, const int* in_sizes, int n_in,
                              void* d_out, int out_size) {
    const float* x      = (const float*)d_in[0];   // [4096, 1024]
    const float* W_enc  = (const float*)d_in[1];   // [16384, 1024]
    const float* W_dict = (const float*)d_in[2];   // [16384, 1024]
    float* out = (float*)d_out;

    __half *xh, *wh, *ch;
    cudaGetSymbolAddress((void**)&xh, g_xh);
    cudaGetSymbolAddress((void**)&wh, g_wh);
    cudaGetSymbolAddress((void**)&ch, g_ch);

    cudaFuncSetAttribute(gemm_kernel, cudaFuncAttributeMaxDynamicSharedMemorySize, GSMEM);

    conv_kernel<<<(NTOK * DMODEL / 4 + 255) / 256, 256>>>(x, xh, NTOK * DMODEL / 4);
    conv_kernel<<<(DICT * DMODEL / 4 + 255) / 256, 256>>>(W_enc, wh, DICT * DMODEL / 4);

    dim3 ggrid(DICT / 128, NTOK / 128);            // (128, 32)
    gemm_kernel<<<ggrid, 256, GSMEM>>>(xh, wh, ch);

    topc_kernel<<<NTOK, 256>>>();
    rescore_kernel<<<NTOK, 256>>>(x, W_enc);
    gather_kernel<<<NTOK, 256>>>(W_dict, out);
    loss_kernel<<<1, 256>>>(out, out_size);
}